// round 1
// baseline (speedup 1.0000x reference)
#include <cuda_runtime.h>
#include <math.h>

// Problem constants
#define LL   2048
#define HH   24
#define DD   128
#define HID  3072
#define MLPD 12288
#define NN1  21504   // 3*HID + MLP
#define NN2  15360   // HID + MLP
#define EPSF 1e-6f

// ---------------- scratch (static device arrays; no allocs) ----------------
__device__ float g_mod[3 * HID];                       // shift|scale|gate
__device__ float g_xmod[(size_t)LL * HID];             // 25 MB
__device__ float g_h[(size_t)LL * NN1];                // 176 MB  (qkv | mlp)
__device__ float g_scores[(size_t)HH * LL * LL];       // 402 MB
__device__ float g_oc[(size_t)LL * NN2];               // 126 MB  (attn | gelu(mlp))

// ---------------- kernel 1: mod = silu(vec) @ mod_w + mod_b ----------------
__global__ void mod_gemv(const float* __restrict__ vec,
                         const float* __restrict__ mod_w,
                         const float* __restrict__ mod_b) {
    __shared__ float sv[HID];
    int tid = threadIdx.x;
    for (int i = tid; i < HID; i += blockDim.x) {
        float a = vec[i];
        sv[i] = a / (1.f + __expf(-a));
    }
    __syncthreads();
    int j = blockIdx.x * blockDim.x + tid;
    float acc = 0.f;
    #pragma unroll 4
    for (int k = 0; k < HID; k++)
        acc += sv[k] * mod_w[(size_t)k * (3 * HID) + j];
    g_mod[j] = acc + mod_b[j];
}

// ---------------- kernel 2: layernorm + modulation ----------------
__global__ void ln_mod_kernel(const float* __restrict__ x,
                              const float* __restrict__ gamma,
                              const float* __restrict__ beta) {
    __shared__ float red[32];
    int l = blockIdx.x;
    const float* xr = x + (size_t)l * HID;
    float s = 0.f, s2 = 0.f;
    for (int i = threadIdx.x; i < HID; i += 256) {
        float v = xr[i];
        s += v; s2 += v * v;
    }
    // block reduce (two values packed sequentially)
    int lane = threadIdx.x & 31, wid = threadIdx.x >> 5;
    #pragma unroll
    for (int o = 16; o; o >>= 1) { s += __shfl_down_sync(~0u, s, o); s2 += __shfl_down_sync(~0u, s2, o); }
    if (lane == 0) { red[wid] = s; red[wid + 8] = s2; }
    __syncthreads();
    float ts = 0.f, ts2 = 0.f;
    if (threadIdx.x < 8) { ts = red[threadIdx.x]; ts2 = red[threadIdx.x + 8]; }
    #pragma unroll
    for (int o = 4; o; o >>= 1) { ts += __shfl_down_sync(0xff, ts, o); ts2 += __shfl_down_sync(0xff, ts2, o); }
    if (threadIdx.x == 0) { red[0] = ts; red[1] = ts2; }
    __syncthreads();
    float mu = red[0] / HID;
    float var = red[1] / HID - mu * mu;
    float rsig = rsqrtf(var + EPSF);
    for (int i = threadIdx.x; i < HID; i += 256) {
        float lnv = (xr[i] - mu) * rsig * gamma[i] + beta[i];
        g_xmod[(size_t)l * HID + i] = (1.f + g_mod[HID + i]) * lnv + g_mod[i];
    }
}

// ---------------- generic 128x128x8 SIMT fp32 GEMM ----------------
// C[m][n] = epi( sum_k A[m][k] * (TB ? B[n][k] : B[k][n]) )
// EPI: 0=none, 1=+bias[n], 2=*alpha, 3=resid[m*HID+n] + gate[n]*(acc+bias[n])
template<bool TB, int EPI>
__global__ void __launch_bounds__(256) sgemm(
    const float* __restrict__ A, int lda, long sA,
    const float* __restrict__ B, int ldb, long sB,
    float* __restrict__ C, int ldc, long sC,
    int K,
    const float* __restrict__ bias, float alpha,
    const float* __restrict__ resid, const float* __restrict__ gate)
{
    A += (long)blockIdx.z * sA;
    B += (long)blockIdx.z * sB;
    C += (long)blockIdx.z * sC;
    __shared__ float As[8][128];
    __shared__ float Bs[8][128];
    int tid = threadIdx.x;
    int row0 = blockIdx.y * 128;
    int col0 = blockIdx.x * 128;
    int tx = tid & 15, ty = tid >> 4;
    float acc[8][8] = {};

    int am = tid >> 1;
    int ak = (tid & 1) * 4;
    int bn, bk;
    if (TB) { bn = tid >> 1;  bk = (tid & 1) * 4; }
    else    { bk = tid >> 5;  bn = (tid & 31) * 4; }

    for (int k0 = 0; k0 < K; k0 += 8) {
        float4 av = *(const float4*)&A[(size_t)(row0 + am) * lda + k0 + ak];
        As[ak + 0][am] = av.x; As[ak + 1][am] = av.y;
        As[ak + 2][am] = av.z; As[ak + 3][am] = av.w;
        if (TB) {
            float4 bv = *(const float4*)&B[(size_t)(col0 + bn) * ldb + k0 + bk];
            Bs[bk + 0][bn] = bv.x; Bs[bk + 1][bn] = bv.y;
            Bs[bk + 2][bn] = bv.z; Bs[bk + 3][bn] = bv.w;
        } else {
            float4 bv = *(const float4*)&B[(size_t)(k0 + bk) * ldb + col0 + bn];
            *(float4*)&Bs[bk][bn] = bv;
        }
        __syncthreads();
        #pragma unroll
        for (int kk = 0; kk < 8; kk++) {
            float4 a0 = *(const float4*)&As[kk][ty * 8];
            float4 a1 = *(const float4*)&As[kk][ty * 8 + 4];
            float4 b0 = *(const float4*)&Bs[kk][tx * 8];
            float4 b1 = *(const float4*)&Bs[kk][tx * 8 + 4];
            float a[8] = {a0.x, a0.y, a0.z, a0.w, a1.x, a1.y, a1.z, a1.w};
            float b[8] = {b0.x, b0.y, b0.z, b0.w, b1.x, b1.y, b1.z, b1.w};
            #pragma unroll
            for (int i = 0; i < 8; i++)
                #pragma unroll
                for (int j = 0; j < 8; j++)
                    acc[i][j] += a[i] * b[j];
        }
        __syncthreads();
    }

    #pragma unroll
    for (int i = 0; i < 8; i++) {
        int m = row0 + ty * 8 + i;
        #pragma unroll
        for (int j = 0; j < 8; j++) {
            int n = col0 + tx * 8 + j;
            float v = acc[i][j];
            if (EPI == 1)      v += bias[n];
            else if (EPI == 2) v *= alpha;
            else if (EPI == 3) v = resid[(size_t)m * HID + n] + gate[n] * (v + bias[n]);
            C[(size_t)m * ldc + n] = v;
        }
    }
}

// ---------------- rmsnorm + rope on q,k (in place in g_h) ----------------
__global__ void rmsnorm_rope(const float* __restrict__ pe,
                             const float* __restrict__ q_scale,
                             const float* __restrict__ k_scale) {
    int l = blockIdx.x, hd = blockIdx.y, which = blockIdx.z;
    const float* sc = which ? k_scale : q_scale;
    size_t base = (size_t)l * NN1 + (size_t)which * HID + (size_t)hd * DD;
    int d = threadIdx.x;   // 128 threads
    float t = g_h[base + d];
    __shared__ float red[4];
    float v = t * t;
    #pragma unroll
    for (int o = 16; o; o >>= 1) v += __shfl_down_sync(~0u, v, o);
    if ((d & 31) == 0) red[d >> 5] = v;
    __syncthreads();
    float ss = red[0] + red[1] + red[2] + red[3];
    float r = rsqrtf(ss / DD + EPSF);
    __shared__ float s[DD];
    s[d] = t * r * sc[d];
    __syncthreads();
    int i = d >> 1, j = d & 1;
    const float* p = pe + (((size_t)l * (DD / 2) + i) * 2 + j) * 2;
    g_h[base + d] = p[0] * s[2 * i] + p[1] * s[2 * i + 1];
}

// ---------------- softmax over rows of g_scores (in place) ----------------
__global__ void softmax_rows() {
    size_t row = blockIdx.x;
    float* p = g_scores + row * LL;
    __shared__ float red[8];
    int lane = threadIdx.x & 31, wid = threadIdx.x >> 5;

    float mx = -1e30f;
    for (int i = threadIdx.x; i < LL; i += 256) mx = fmaxf(mx, p[i]);
    #pragma unroll
    for (int o = 16; o; o >>= 1) mx = fmaxf(mx, __shfl_down_sync(~0u, mx, o));
    if (lane == 0) red[wid] = mx;
    __syncthreads();
    if (threadIdx.x < 8) {
        float m = red[threadIdx.x];
        #pragma unroll
        for (int o = 4; o; o >>= 1) m = fmaxf(m, __shfl_down_sync(0xff, m, o));
        if (threadIdx.x == 0) red[0] = m;
    }
    __syncthreads();
    mx = red[0];
    __syncthreads();

    float sum = 0.f;
    for (int i = threadIdx.x; i < LL; i += 256) {
        float e = __expf(p[i] - mx);
        p[i] = e; sum += e;
    }
    #pragma unroll
    for (int o = 16; o; o >>= 1) sum += __shfl_down_sync(~0u, sum, o);
    if (lane == 0) red[wid] = sum;
    __syncthreads();
    if (threadIdx.x < 8) {
        float t = red[threadIdx.x];
        #pragma unroll
        for (int o = 4; o; o >>= 1) t += __shfl_down_sync(0xff, t, o);
        if (threadIdx.x == 0) red[0] = t;
    }
    __syncthreads();
    float inv = 1.f / red[0];
    for (int i = threadIdx.x; i < LL; i += 256) p[i] *= inv;
}

// ---------------- gelu(mlp) -> g_oc second half ----------------
__global__ void gelu_copy() {
    size_t idx = (size_t)blockIdx.x * 256 + threadIdx.x;   // L*MLP total
    size_t l = idx / MLPD;
    size_t m = idx % MLPD;
    float v = g_h[l * NN1 + 3 * HID + m];
    float c = 0.7978845608028654f * (v + 0.044715f * v * v * v);
    g_oc[l * NN2 + HID + m] = 0.5f * v * (1.f + tanhf(c));
}

// ---------------- launcher ----------------
extern "C" void kernel_launch(void* const* d_in, const int* in_sizes, int n_in,
                              void* d_out, int out_size) {
    const float* x       = (const float*)d_in[0];
    const float* vec     = (const float*)d_in[1];
    const float* pe      = (const float*)d_in[2];
    const float* mod_w   = (const float*)d_in[3];
    const float* mod_b   = (const float*)d_in[4];
    const float* gamma   = (const float*)d_in[5];
    const float* beta    = (const float*)d_in[6];
    const float* w1      = (const float*)d_in[7];
    const float* b1      = (const float*)d_in[8];
    const float* q_scale = (const float*)d_in[9];
    const float* k_scale = (const float*)d_in[10];
    const float* w2      = (const float*)d_in[11];
    const float* b2      = (const float*)d_in[12];
    float* out = (float*)d_out;

    float *p_xmod, *p_h, *p_scores, *p_oc, *p_mod;
    cudaGetSymbolAddress((void**)&p_xmod,   g_xmod);
    cudaGetSymbolAddress((void**)&p_h,      g_h);
    cudaGetSymbolAddress((void**)&p_scores, g_scores);
    cudaGetSymbolAddress((void**)&p_oc,     g_oc);
    cudaGetSymbolAddress((void**)&p_mod,    g_mod);

    // 1) modulation GEMV
    mod_gemv<<<(3 * HID) / 256, 256>>>(vec, mod_w, mod_b);
    // 2) layernorm + modulation
    ln_mod_kernel<<<LL, 256>>>(x, gamma, beta);
    // 3) h = x_mod @ w1 + b1     (M=2048, N=21504, K=3072)
    sgemm<false, 1><<<dim3(NN1 / 128, LL / 128, 1), 256>>>(
        p_xmod, HID, 0, w1, NN1, 0, p_h, NN1, 0, HID, b1, 1.f, nullptr, nullptr);
    // 4) rmsnorm + rope on q and k (in place)
    rmsnorm_rope<<<dim3(LL, HH, 2), 128>>>(pe, q_scale, k_scale);
    // 5) scores = q @ k^T * D^-0.5   (batched over heads, NT)
    sgemm<true, 2><<<dim3(LL / 128, LL / 128, HH), 256>>>(
        p_h, NN1, 128, p_h + HID, NN1, 128,
        p_scores, LL, (long)LL * LL, DD, nullptr, 0.08838834764831845f, nullptr, nullptr);
    // 6) softmax
    softmax_rows<<<HH * LL, 256>>>();
    // 7) attn = P @ v  -> first HID cols of g_oc   (batched, NN)
    sgemm<false, 0><<<dim3(1, LL / 128, HH), 256>>>(
        p_scores, LL, (long)LL * LL, p_h + 2 * HID, NN1, 128,
        p_oc, NN2, 128, LL, nullptr, 1.f, nullptr, nullptr);
    // 8) gelu(mlp) -> rest of g_oc
    gelu_copy<<<((size_t)LL * MLPD) / 256, 256>>>();
    // 9) out = x + gate * (g_oc @ w2 + b2)   (M=2048, N=3072, K=15360)
    sgemm<false, 3><<<dim3(HID / 128, LL / 128, 1), 256>>>(
        p_oc, NN2, 0, w2, HID, 0, out, HID, 0, NN2,
        b2, 1.f, x, p_mod + 2 * HID);
}